// round 8
// baseline (speedup 1.0000x reference)
#include <cuda_runtime.h>
#include <stdint.h>

// Pre-emphasis IIR y[i] = x[i] + 0.85*y[i-1]; out[o] = float(clip_int16(32768*y[o+91])),
// out[N-91..] = 0.
// R8: register-only formulation. Lane owns 4 contiguous samples (coalesced float4),
// +91 shift realigned via shuffles, Kogge-Stone weighted warp scan for carries,
// cross-window carry s = P31 (0.85^128 ~ 2e-10 -> windows independent). No smem.
// L1 wavefronts drop ~3.3x (strided LDG + 2 smem passes eliminated).

namespace {
constexpr int   kBlock = 256;
constexpr int   kWin   = 128;                  // outputs per warp window
constexpr int   kIter  = 32;                   // windows per warp segment
constexpr int   kSeg   = kWin * kIter;         // 4096 outputs per warp
constexpr int   kSkip  = 91;
constexpr float C1     = 0.85f;

constexpr float cp(int k) {
    float r = 1.0f;
    for (int i = 0; i < k; ++i) r *= 0.85f;
    return r;
}
// correction coefficients (state contribution to lane-local samples 0..3)
constexpr float A1 = cp(1), A2 = cp(2), A3 = cp(3), A4 = cp(4);
// Kogge-Stone merge weights: block of 2^k lanes * 4 samples
constexpr float K1 = cp(4), K2 = cp(8), K3 = cp(16), K4 = cp(32), K5 = cp(64);
}

// Saturating truncate-toward-zero to int16 range, back to float.
// Matches clip(-32768,32767) + astype(int16) exactly (f32->s16 cvt saturates).
__device__ __forceinline__ float q16(float v) {
    short q; asm("cvt.rzi.s16.f32 %0, %1;" : "=h"(q) : "f"(v));
    float r; asm("cvt.rn.f32.s16 %0, %1;" : "=f"(r) : "h"(q));
    return r;
}

template <bool EDGE>
__device__ __forceinline__ float4 ld4(const float* __restrict__ x, int e0, int n) {
    if (!EDGE) return *reinterpret_cast<const float4*>(x + e0);
    float4 v;
    v.x = (e0 + 0 >= 0 && e0 + 0 < n) ? x[e0 + 0] : 0.0f;
    v.y = (e0 + 1 >= 0 && e0 + 1 < n) ? x[e0 + 1] : 0.0f;
    v.z = (e0 + 2 >= 0 && e0 + 2 < n) ? x[e0 + 2] : 0.0f;
    v.w = (e0 + 3 >= 0 && e0 + 3 < n) ? x[e0 + 3] : 0.0f;
    return v;
}

template <bool EDGE>
__device__ __forceinline__ void seg_body(const float* __restrict__ x,
                                         float* __restrict__ out,
                                         int n, int nout, int W0, int l, float c4l)
{
    const unsigned FULL = 0xffffffffu;
    float s = 0.0f;
    // warmup window w=-1 load: covers x[W0-40+4l .. +4)
    float4 cur = ld4<EDGE>(x, W0 - kWin + 88 + 4 * l, n);

    #pragma unroll 4
    for (int w = -1; w < kIter; ++w) {
        // lookahead load (also supplies lane31's realign tail)
        float4 nxt = ld4<EDGE>(x, W0 + (w + 1) * kWin + 88 + 4 * l, n);

        // realign +3: lane l's samples = {cur.w, lane(l+1).cur.x/.y/.z}
        float ax = __shfl_down_sync(FULL, cur.x, 1);
        float ay = __shfl_down_sync(FULL, cur.y, 1);
        float az = __shfl_down_sync(FULL, cur.z, 1);
        float bx = __shfl_sync(FULL, nxt.x, 0);
        float by = __shfl_sync(FULL, nxt.y, 0);
        float bz = __shfl_sync(FULL, nxt.z, 0);
        if (l == 31) { ax = bx; ay = by; az = bz; }

        // lane-local scan of 4 samples (pre-scaled by 32768), zero entry state
        float y0 = 32768.0f * cur.w;
        float y1 = fmaf(C1, y0, 32768.0f * ax);
        float y2 = fmaf(C1, y1, 32768.0f * ay);
        float y3 = fmaf(C1, y2, 32768.0f * az);

        // Kogge-Stone weighted inclusive scan of end-states over lanes
        float P = y3, u;
        u = __shfl_up_sync(FULL, P, 1);  P = (l >= 1)  ? fmaf(K1, u, P) : P;
        u = __shfl_up_sync(FULL, P, 2);  P = (l >= 2)  ? fmaf(K2, u, P) : P;
        u = __shfl_up_sync(FULL, P, 4);  P = (l >= 4)  ? fmaf(K3, u, P) : P;
        u = __shfl_up_sync(FULL, P, 8);  P = (l >= 8)  ? fmaf(K4, u, P) : P;
        u = __shfl_up_sync(FULL, P, 16); P = (l >= 16) ? fmaf(K5, u, P) : P;

        // entering state for this lane: E = c^(4l)*s + P_{l-1}
        float Pex = __shfl_up_sync(FULL, P, 1);
        float E = fmaf(c4l, s, (l == 0) ? 0.0f : Pex);
        // carry for next window (0.85^128*s term negligible -> independent)
        s = __shfl_sync(FULL, P, 31);

        if (w >= 0) {
            float4 o;
            o.x = q16(fmaf(A1, E, y0));
            o.y = q16(fmaf(A2, E, y1));
            o.z = q16(fmaf(A3, E, y2));
            o.w = q16(fmaf(A4, E, y3));
            if (!EDGE) {
                reinterpret_cast<float4*>(out)[(W0 + w * kWin) / 4 + l] = o;
            } else {
                const int oi = W0 + w * kWin + 4 * l;
                const int zf = n - kSkip;     // outputs at/after this are 0
                float v[4] = {o.x, o.y, o.z, o.w};
                #pragma unroll
                for (int e = 0; e < 4; ++e)
                    if (oi + e < nout)
                        out[oi + e] = (oi + e < zf) ? v[e] : 0.0f;
            }
        }
        cur = nxt;
    }
}

__global__ __launch_bounds__(kBlock, 8)
void preemph_f32_kernel(const float* __restrict__ x, float* __restrict__ out,
                        int n, int nout)
{
    const int wg = (blockIdx.x * kBlock + threadIdx.x) >> 5;
    const int l  = threadIdx.x & 31;
    const int W0 = wg * kSeg;
    if (W0 >= nout) return;

    // c^(4l) per lane via bit decomposition (5 predicated multiplies)
    float c4l = 1.0f;
    if (l & 1)  c4l *= K1;   // c^4
    if (l & 2)  c4l *= K2;   // c^8
    if (l & 4)  c4l *= K3;   // c^16
    if (l & 8)  c4l *= K4;   // c^32
    if (l & 16) c4l *= K5;   // c^64

    const bool edge = (W0 == 0) || (W0 + kSeg + 256 > n) || (W0 + kSeg > nout);
    if (edge) seg_body<true >(x, out, n, nout, W0, l, c4l);
    else      seg_body<false>(x, out, n, nout, W0, l, c4l);
}

extern "C" void kernel_launch(void* const* d_in, const int* in_sizes, int n_in,
                              void* d_out, int out_size) {
    const float* x = (const float*)d_in[0];
    float* out = (float*)d_out;
    const int n = in_sizes[0];
    const int warps = (out_size + kSeg - 1) / kSeg;
    const int grid = (warps + (kBlock / 32) - 1) / (kBlock / 32);
    preemph_f32_kernel<<<grid, kBlock>>>(x, out, n, out_size);
}